// round 1
// baseline (speedup 1.0000x reference)
#include <cuda_runtime.h>
#include <stdint.h>

typedef unsigned long long ULL;

__device__ __forceinline__ ULL fma2(ULL a, ULL b, ULL c) {
    ULL d;
    asm("fma.rn.f32x2 %0, %1, %2, %3;" : "=l"(d) : "l"(a), "l"(b), "l"(c));
    return d;
}
__device__ __forceinline__ ULL pack2(unsigned lo, unsigned hi) {
    ULL r;
    asm("mov.b64 %0, {%1, %2};" : "=l"(r) : "r"(lo), "r"(hi));
    return r;
}
__device__ __forceinline__ void unpack2(ULL v, unsigned &lo, unsigned &hi) {
    asm("mov.b64 {%0, %1}, %2;" : "=r"(lo), "=r"(hi) : "l"(v));
}

// Problem constants
#define N_BATCH 64
#define C_IN    8
#define HW      256
#define M_OUT   8
#define P_OUT   254   // 256 - 3 + 1

// Tiling: 64 cols x 32 rows of output per block, one n, all 8 m.
// 256 threads as 16x16; each thread: 4 cols x 2 rows x 8 m = 32 f32x2 accumulators.
#define TILE_X 64
#define TILE_Y 32
#define IN_W   68     // 66 needed (64+2 halo), padded to 68 (even, float2-aligned rows)
#define IN_H   34     // 32 + 2 halo
#define SMEM_IN_FLOATS (C_IN * IN_H * IN_W)      // 18496 floats
#define SMEM_BYTES (576 * 8 + SMEM_IN_FLOATS * 4) // 4608 + 73984 = 78592

__global__ __launch_bounds__(256, 2)
void im2col_conv2d_kernel(const float* __restrict__ in,
                          const float* __restrict__ flt,
                          float* __restrict__ out) {
    extern __shared__ ULL smem[];
    ULL*   ws   = smem;                          // 576 splatted weights {w,w}
    float* sin_ = (float*)(smem + 576);          // input tile

    const int tid = threadIdx.x;
    const int n  = blockIdx.z;
    const int y0 = blockIdx.y * TILE_Y;
    const int x0 = blockIdx.x * TILE_X;

    // ---- stage weights, splatted into both f32x2 lanes ----
    // filter layout OIHW: i = ((m*8 + c)*3 + r)*3 + s
    for (int i = tid; i < 576; i += 256) {
        int s = i % 3;
        int t = i / 3;
        int r = t % 3; t /= 3;
        int c = t & 7;
        int m = t >> 3;
        unsigned w = __float_as_uint(flt[i]);
        ws[((c * 8 + m) * 3 + r) * 3 + s] = pack2(w, w);
    }

    // ---- stage input tile (zero-fill halo out of range) ----
    const float* inb = in + (size_t)n * C_IN * HW * HW;
    for (int i = tid; i < SMEM_IN_FLOATS; i += 256) {
        int col = i % IN_W;
        int t   = i / IN_W;
        int row = t % IN_H;
        int c   = t / IN_H;
        int gy = y0 + row, gx = x0 + col;
        float v = 0.f;
        if (gy < HW && gx < HW) v = inb[(c * HW + gy) * HW + gx];
        sin_[i] = v;
    }
    __syncthreads();

    const int tx = tid & 15;   // 0..15 -> cols 4*tx .. 4*tx+3
    const int ty = tid >> 4;   // 0..15 -> rows 2*ty, 2*ty+1

    ULL acc[8][2][2];
    #pragma unroll
    for (int m = 0; m < 8; m++)
        #pragma unroll
        for (int o = 0; o < 2; o++)
            #pragma unroll
            for (int p = 0; p < 2; p++)
                acc[m][o][p] = 0ull;

    #pragma unroll 1
    for (int c = 0; c < C_IN; c++) {
        const float* p = sin_ + c * (IN_H * IN_W) + (2 * ty) * IN_W + 4 * tx;

        // 4 input rows x 6 cols each, as aligned f32x2 pairs + shifted repacks
        ULL e[4][3], od[4][2];
        #pragma unroll
        for (int ir = 0; ir < 4; ir++) {
            ULL a = *(const ULL*)(p + ir * IN_W);       // cols x..x+1
            ULL b = *(const ULL*)(p + ir * IN_W + 2);   // cols x+2..x+3
            ULL d = *(const ULL*)(p + ir * IN_W + 4);   // cols x+4..x+5
            e[ir][0] = a; e[ir][1] = b; e[ir][2] = d;
            unsigned alo, ahi, blo, bhi, dlo, dhi;
            unpack2(a, alo, ahi);
            unpack2(b, blo, bhi);
            unpack2(d, dlo, dhi);
            od[ir][0] = pack2(ahi, blo);  // cols x+1..x+2
            od[ir][1] = pack2(bhi, dlo);  // cols x+3..x+4
        }

        const ULL* w = ws + c * 72;  // [m][r][s]
        #pragma unroll
        for (int r = 0; r < 3; r++) {
            #pragma unroll
            for (int m = 0; m < 8; m++) {
                ULL w0 = w[(m * 3 + r) * 3 + 0];
                ULL w1 = w[(m * 3 + r) * 3 + 1];
                ULL w2 = w[(m * 3 + r) * 3 + 2];
                // output row o uses input row r+o
                acc[m][0][0] = fma2(e[r][0],     w0, acc[m][0][0]);
                acc[m][0][1] = fma2(e[r][1],     w0, acc[m][0][1]);
                acc[m][1][0] = fma2(e[r + 1][0], w0, acc[m][1][0]);
                acc[m][1][1] = fma2(e[r + 1][1], w0, acc[m][1][1]);

                acc[m][0][0] = fma2(od[r][0],     w1, acc[m][0][0]);
                acc[m][0][1] = fma2(od[r][1],     w1, acc[m][0][1]);
                acc[m][1][0] = fma2(od[r + 1][0], w1, acc[m][1][0]);
                acc[m][1][1] = fma2(od[r + 1][1], w1, acc[m][1][1]);

                acc[m][0][0] = fma2(e[r][1],     w2, acc[m][0][0]);
                acc[m][0][1] = fma2(e[r][2],     w2, acc[m][0][1]);
                acc[m][1][0] = fma2(e[r + 1][1], w2, acc[m][1][0]);
                acc[m][1][1] = fma2(e[r + 1][2], w2, acc[m][1][1]);
            }
        }
    }

    // ---- store: float2 stores (offsets are always even -> 8B aligned) ----
    const int x = x0 + 4 * tx;
    #pragma unroll
    for (int m = 0; m < 8; m++) {
        float* ob = out + ((size_t)(n * M_OUT + m)) * P_OUT * P_OUT;
        #pragma unroll
        for (int o = 0; o < 2; o++) {
            int y = y0 + 2 * ty + o;
            if (y < P_OUT) {
                unsigned l0, h0;
                unpack2(acc[m][o][0], l0, h0);
                *(float2*)(ob + (size_t)y * P_OUT + x) =
                    make_float2(__uint_as_float(l0), __uint_as_float(h0));
                if (x + 3 < P_OUT) {
                    unsigned l1, h1;
                    unpack2(acc[m][o][1], l1, h1);
                    *(float2*)(ob + (size_t)y * P_OUT + x + 2) =
                        make_float2(__uint_as_float(l1), __uint_as_float(h1));
                }
                // (x == 252 case: cols 254/255 do not exist; pair0 covers 252,253)
            }
        }
    }
}

extern "C" void kernel_launch(void* const* d_in, const int* in_sizes, int n_in,
                              void* d_out, int out_size) {
    const float* in  = (const float*)d_in[0];   // (64, 8, 256, 256) fp32
    const float* flt = (const float*)d_in[1];   // (8, 8, 3, 3) fp32
    float* out = (float*)d_out;                 // (64, 8, 254, 254) fp32

    (void)in_sizes; (void)n_in; (void)out_size;

    cudaFuncSetAttribute(im2col_conv2d_kernel,
                         cudaFuncAttributeMaxDynamicSharedMemorySize, SMEM_BYTES);

    dim3 grid(4, 8, N_BATCH);  // ceil(254/64)=4 col tiles, ceil(254/32)=8 row tiles, 64 n
    im2col_conv2d_kernel<<<grid, 256, SMEM_BYTES>>>(in, flt, out);
}

// round 2
// speedup vs baseline: 1.2764x; 1.2764x over previous
#include <cuda_runtime.h>
#include <stdint.h>

typedef unsigned long long ULL;

__device__ __forceinline__ ULL fma2(ULL a, ULL b, ULL c) {
    ULL d;
    asm("fma.rn.f32x2 %0, %1, %2, %3;" : "=l"(d) : "l"(a), "l"(b), "l"(c));
    return d;
}
__device__ __forceinline__ ULL pack2(unsigned lo, unsigned hi) {
    ULL r;
    asm("mov.b64 %0, {%1, %2};" : "=l"(r) : "r"(lo), "r"(hi));
    return r;
}
__device__ __forceinline__ void unpack2(ULL v, unsigned &lo, unsigned &hi) {
    asm("mov.b64 {%0, %1}, %2;" : "=r"(lo), "=r"(hi) : "l"(v));
}

// Problem constants
#define N_BATCH 64
#define C_IN    8
#define HW      256
#define M_OUT   8
#define P_OUT   254

// Block: 128 threads = 16 tx * 8 ty. Tile: 32 cols (2 per tx) x 16 rows (2 per ty).
// Each thread: 8 m * 2 rows * 1 f32x2 pair (2 cols) = 16 f32x2 accumulators (32 regs).
#define TILE_X 32
#define TILE_Y 16
#define IN_W   36     // 32 + 2 halo, padded to even
#define IN_H   18     // 16 + 2 halo
#define SMEM_IN_FLOATS (C_IN * IN_H * IN_W)   // 5184 floats = 20736 B
// weights: [c][m][r*3+s] splatted ULL: 8*8*9 = 576 ULL = 4608 B
// total static smem = 25344 B  -> fits default 48KB, ~5 blocks/SM by smem

__global__ __launch_bounds__(128)
void im2col_conv2d_kernel(const float* __restrict__ in,
                          const float* __restrict__ flt,
                          float* __restrict__ out) {
    __shared__ ULL   ws[576];
    __shared__ float sin_[SMEM_IN_FLOATS];

    const int tid = threadIdx.x;
    const int n  = blockIdx.z;
    const int y0 = blockIdx.y * TILE_Y;
    const int x0 = blockIdx.x * TILE_X;

    // ---- stage weights, splatted into both f32x2 lanes ----
    // filter OIHW: i = ((m*8 + c)*3 + r)*3 + s  ->  ws[(c*8 + m)*9 + r*3 + s]
    for (int i = tid; i < 576; i += 128) {
        int s = i % 3;
        int t = i / 3;
        int r = t % 3; t /= 3;
        int c = t & 7;
        int m = t >> 3;
        unsigned w = __float_as_uint(flt[i]);
        ws[(c * 8 + m) * 9 + r * 3 + s] = pack2(w, w);
    }

    // ---- stage input tile (zero-fill out of range) ----
    const float* inb = in + (size_t)n * C_IN * HW * HW;
    for (int i = tid; i < SMEM_IN_FLOATS; i += 128) {
        int col = i % IN_W;
        int t   = i / IN_W;
        int row = t % IN_H;
        int c   = t / IN_H;
        int gy = y0 + row, gx = x0 + col;
        float v = 0.f;
        if (gy < HW && gx < HW) v = inb[(c * HW + gy) * HW + gx];
        sin_[i] = v;
    }
    __syncthreads();

    const int tx = tid & 15;   // cols: x = x0 + 2*tx .. +1
    const int ty = tid >> 4;   // rows: y = y0 + 2*ty .. +1

    ULL acc[8][2];
    #pragma unroll
    for (int m = 0; m < 8; m++) {
        acc[m][0] = 0ull;
        acc[m][1] = 0ull;
    }

    #pragma unroll 1
    for (int c = 0; c < C_IN; c++) {
        const float* p = sin_ + c * (IN_H * IN_W) + (2 * ty) * IN_W + 2 * tx;

        // 4 input rows; per row: aligned pairs a=(x,x+1), b=(x+2,x+3), shifted od=(x+1,x+2)
        ULL a[4], b[4], od[4];
        #pragma unroll
        for (int ir = 0; ir < 4; ir++) {
            a[ir] = *(const ULL*)(p + ir * IN_W);
            b[ir] = *(const ULL*)(p + ir * IN_W + 2);
        }
        #pragma unroll
        for (int ir = 0; ir < 4; ir++) {
            unsigned alo, ahi, blo, bhi;
            unpack2(a[ir], alo, ahi);
            unpack2(b[ir], blo, bhi);
            od[ir] = pack2(ahi, blo);
        }

        const ULL* wc = ws + c * 72;
        #pragma unroll
        for (int m = 0; m < 8; m++) {
            // batch all 9 weights for this (c,m) -> single MLP=9 latency window
            ULL wr[9];
            #pragma unroll
            for (int k = 0; k < 9; k++) wr[k] = wc[m * 9 + k];

            #pragma unroll
            for (int r = 0; r < 3; r++) {
                // out row 0 uses input row r; out row 1 uses input row r+1
                acc[m][0] = fma2(a[r],      wr[3 * r + 0], acc[m][0]);
                acc[m][1] = fma2(a[r + 1],  wr[3 * r + 0], acc[m][1]);
                acc[m][0] = fma2(od[r],     wr[3 * r + 1], acc[m][0]);
                acc[m][1] = fma2(od[r + 1], wr[3 * r + 1], acc[m][1]);
                acc[m][0] = fma2(b[r],      wr[3 * r + 2], acc[m][0]);
                acc[m][1] = fma2(b[r + 1],  wr[3 * r + 2], acc[m][1]);
            }
        }
    }

    // ---- stores: guarded STG.64 (x even, row stride 254 -> (y*254+x) even -> 8B aligned) ----
    const int x = x0 + 2 * tx;
    if (x < P_OUT) {
        #pragma unroll
        for (int m = 0; m < 8; m++) {
            float* ob = out + ((size_t)(n * M_OUT + m)) * P_OUT * P_OUT;
            #pragma unroll
            for (int o = 0; o < 2; o++) {
                int y = y0 + 2 * ty + o;
                if (y < P_OUT) {
                    unsigned lo, hi;
                    unpack2(acc[m][o], lo, hi);
                    *(float2*)(ob + (size_t)y * P_OUT + x) =
                        make_float2(__uint_as_float(lo), __uint_as_float(hi));
                }
            }
        }
    }
}

extern "C" void kernel_launch(void* const* d_in, const int* in_sizes, int n_in,
                              void* d_out, int out_size) {
    const float* in  = (const float*)d_in[0];   // (64, 8, 256, 256) fp32
    const float* flt = (const float*)d_in[1];   // (8, 8, 3, 3) fp32
    float* out = (float*)d_out;                 // (64, 8, 254, 254) fp32

    (void)in_sizes; (void)n_in; (void)out_size;

    // grid: 254/32 -> 8 col tiles, 254/16 -> 16 row tiles, 64 batches
    dim3 grid(8, 16, N_BATCH);
    im2col_conv2d_kernel<<<grid, 128>>>(in, flt, out);
}

// round 4
// speedup vs baseline: 1.6539x; 1.2957x over previous
#include <cuda_runtime.h>
#include <stdint.h>

typedef unsigned long long ULL;

__device__ __forceinline__ ULL fma2(ULL a, ULL b, ULL c) {
    ULL d;
    asm("fma.rn.f32x2 %0, %1, %2, %3;" : "=l"(d) : "l"(a), "l"(b), "l"(c));
    return d;
}
__device__ __forceinline__ ULL pack2(unsigned lo, unsigned hi) {
    ULL r;
    asm("mov.b64 %0, {%1, %2};" : "=l"(r) : "r"(lo), "r"(hi));
    return r;
}
__device__ __forceinline__ void unpack2(ULL v, unsigned &lo, unsigned &hi) {
    asm("mov.b64 {%0, %1}, %2;" : "=r"(lo), "=r"(hi) : "l"(v));
}

// Problem constants
#define N_BATCH 64
#define C_IN    8
#define HW      256
#define M_OUT   8
#define P_OUT   254

// Tile: 32 cols x 16 rows x all 8 m per block. 128 threads.
// Thread layout (conflict-aware): lane = txi(8) x g(2) x dty(2); tyi = warp*2+dty.
// Each thread: 4 m (g selects half) x 2 out rows x 4 cols (2 f32x2 pairs) = 16 ULL accs.
#define TILE_X 32
#define TILE_Y 16
#define IN_W   36          // 32 + 2 halo + pad (9 float4 per row)
#define IN_H   18          // 16 + 2 halo
#define C_STRIDE (IN_H * IN_W)          // 648 floats
#define SMEM_IN  (C_IN * C_STRIDE)      // 5184 floats

__global__ __launch_bounds__(128, 4)
void im2col_conv2d_kernel(const float* __restrict__ in,
                          const float* __restrict__ flt,
                          float* __restrict__ out) {
    __shared__ ULL   ws[584];           // [m]*73 + c*9 + r*3 + s  (pad 1 ULL per m)
    __shared__ float sin_[SMEM_IN];     // [c][row][col]

    const int tid = threadIdx.x;
    const int n  = blockIdx.z;
    const int y0 = blockIdx.y * TILE_Y;
    const int x0 = blockIdx.x * TILE_X;

    // ---- weights: identity-order copy, splatted, +m padding for bank split ----
    for (int i = tid; i < 576; i += 128) {
        unsigned w = __float_as_uint(flt[i]);
        ws[i + i / 72] = pack2(w, w);   // i/72 == m
    }

    // ---- input staging: float4 rows, predicated OOB (all-or-nothing per float4) ----
    const float* inb = in + (size_t)n * (C_IN * HW * HW);
    {
        const int lane = tid & 31, warp = tid >> 5;
        if (lane < 27) {
            const int col4 = lane % 9;          // float4 index in row
            const int rsub = lane / 9;          // 0..2
            const int rl0  = warp * 3 + rsub;   // starting row_lin
            const int gx   = x0 + col4 * 4;
            const bool xok = gx < HW;
            #pragma unroll
            for (int pass = 0; pass < 12; pass++) {
                int row_lin = rl0 + pass * 12;      // 0..143 = c*18 + r
                int c = row_lin / 18;
                int r = row_lin - c * 18;
                int gy = y0 + r;
                float4 v = make_float4(0.f, 0.f, 0.f, 0.f);
                if (xok && gy < HW)
                    v = *(const float4*)(inb + (c * HW + gy) * HW + gx);
                *(float4*)(sin_ + c * C_STRIDE + r * IN_W + col4 * 4) = v;
            }
        }
    }
    __syncthreads();

    // ---- compute thread coords ----
    const int lane  = tid & 31;
    const int txi   = lane & 7;                      // col group: x = x0 + 4*txi
    const int g     = (lane >> 3) & 1;               // m half: m = g*4 + mi
    const int tyi   = ((tid >> 5) << 1) | (lane >> 4); // 0..7: rows y0+2*tyi, +1
    const int mbase = g * 4;

    ULL acc[4][2][2];
    #pragma unroll
    for (int mi = 0; mi < 4; mi++)
        #pragma unroll
        for (int o = 0; o < 2; o++) {
            acc[mi][o][0] = 0ull;
            acc[mi][o][1] = 0ull;
        }

    #pragma unroll 1
    for (int c = 0; c < C_IN; c++) {
        const float* p = sin_ + c * C_STRIDE + (2 * tyi) * IN_W + txi * 4;

        // 4 input rows x 6 cols: aligned pairs A=(x,x+1) B=(x+2,x+3) D=(x+4,x+5),
        // shifted O0=(x+1,x+2) O1=(x+3,x+4)
        ULL A[4], B[4], D[4], O0[4], O1[4];
        #pragma unroll
        for (int ir = 0; ir < 4; ir++) {
            A[ir] = *(const ULL*)(p + ir * IN_W);
            B[ir] = *(const ULL*)(p + ir * IN_W + 2);
            D[ir] = *(const ULL*)(p + ir * IN_W + 4);
        }
        #pragma unroll
        for (int ir = 0; ir < 4; ir++) {
            unsigned al, ah, bl, bh, dl, dh;
            unpack2(A[ir], al, ah);
            unpack2(B[ir], bl, bh);
            unpack2(D[ir], dl, dh);
            O0[ir] = pack2(ah, bl);
            O1[ir] = pack2(bh, dl);
        }

        #pragma unroll
        for (int mi = 0; mi < 4; mi++) {
            const ULL* wp = ws + (mbase + mi) * 73 + c * 9;
            ULL wr[9];
            #pragma unroll
            for (int k = 0; k < 9; k++) wr[k] = wp[k];

            #pragma unroll
            for (int r = 0; r < 3; r++) {
                #pragma unroll
                for (int o = 0; o < 2; o++) {
                    const int ir = r + o;
                    acc[mi][o][0] = fma2(A[ir],  wr[3 * r + 0], acc[mi][o][0]);
                    acc[mi][o][0] = fma2(O0[ir], wr[3 * r + 1], acc[mi][o][0]);
                    acc[mi][o][0] = fma2(B[ir],  wr[3 * r + 2], acc[mi][o][0]);
                    acc[mi][o][1] = fma2(B[ir],  wr[3 * r + 0], acc[mi][o][1]);
                    acc[mi][o][1] = fma2(O1[ir], wr[3 * r + 1], acc[mi][o][1]);
                    acc[mi][o][1] = fma2(D[ir],  wr[3 * r + 2], acc[mi][o][1]);
                }
            }
        }
    }

    // ---- stores: STG.64, (y*254 + x) always even -> 8B aligned ----
    const int x = x0 + txi * 4;
    #pragma unroll
    for (int mi = 0; mi < 4; mi++) {
        float* ob = out + (size_t)(n * M_OUT + mbase + mi) * (P_OUT * P_OUT);
        #pragma unroll
        for (int o = 0; o < 2; o++) {
            const int y = y0 + 2 * tyi + o;
            if (y < P_OUT) {
                unsigned lo, hi;
                unpack2(acc[mi][o][0], lo, hi);
                *(float2*)(ob + y * P_OUT + x) =
                    make_float2(__uint_as_float(lo), __uint_as_float(hi));
                if (x < P_OUT - 3) {
                    unpack2(acc[mi][o][1], lo, hi);
                    *(float2*)(ob + y * P_OUT + x + 2) =
                        make_float2(__uint_as_float(lo), __uint_as_float(hi));
                }
            }
        }
    }
}

extern "C" void kernel_launch(void* const* d_in, const int* in_sizes, int n_in,
                              void* d_out, int out_size) {
    const float* in  = (const float*)d_in[0];   // (64, 8, 256, 256) fp32
    const float* flt = (const float*)d_in[1];   // (8, 8, 3, 3) fp32
    float* out = (float*)d_out;                 // (64, 8, 254, 254) fp32

    (void)in_sizes; (void)n_in; (void)out_size;

    dim3 grid(8, 16, N_BATCH);   // 254/32 -> 8, 254/16 -> 16, 64 batches
    im2col_conv2d_kernel<<<grid, 128>>>(in, flt, out);
}

// round 6
// speedup vs baseline: 2.8243x; 1.7077x over previous
#include <cuda_runtime.h>
#include <stdint.h>

// ---------------- problem constants ----------------
#define C_IN   8
#define HW     256
#define M_OUT  8
#define P_OUT  254
#define PLANE  (P_OUT * P_OUT)

// ---------------- tiling ----------------
#define YB        8                        // output rows per block
#define ROWS_ST   (YB + 2)                 // staged input rows
#define CH_STRIDE 264                      // floats; 264 mod 32 == 8 -> conflict-free
#define ROW_STRIDE (C_IN * CH_STRIDE)      // 2112 floats per staged input row
#define SMEM_FLOATS (ROWS_ST * ROW_STRIDE) // 21120
#define SMEM_BYTES  (SMEM_FLOATS * 4)      // 84480

__device__ __forceinline__ uint32_t f2tf32(float f) {
    uint32_t r;
    asm("cvt.rna.tf32.f32 %0, %1;" : "=r"(r) : "f"(f));
    return r;
}

__global__ __launch_bounds__(256, 2)
void conv_mma_kernel(const float* __restrict__ in,
                     const float* __restrict__ flt,
                     float* __restrict__ out) {
    extern __shared__ float sin_[];   // [row 0..9][c 0..7][px, stride 264]

    const int tid  = threadIdx.x;
    const int w    = tid >> 5;
    const int lane = tid & 31;
    const int gid  = lane >> 2;       // 0..7
    const int tig  = lane & 3;        // 0..3
    const int n    = blockIdx.y;
    const int y0   = blockIdx.x * YB;

    // ---- stage input rows y0 .. y0+9 (zero-fill past image bottom) ----
    const float* inb = in + (size_t)n * (C_IN * HW * HW);
    #pragma unroll
    for (int it = 0; it < 20; it++) {
        int i   = tid + it * 256;     // 0..5119
        int row = i >> 9;             // /512 : 10 rows
        int c   = (i >> 6) & 7;
        int x4  = i & 63;             // float4 within row
        int gy  = y0 + row;
        float4 v = make_float4(0.f, 0.f, 0.f, 0.f);
        if (gy < HW) v = *(const float4*)(inb + (c * HW + gy) * HW + x4 * 4);
        *(float4*)(sin_ + row * ROW_STRIDE + c * CH_STRIDE + x4 * 4) = v;
    }

    // ---- B fragments (weights), resident for whole block ----
    // mma m16n8k8 B layout: b0 = B[k=tig][n=gid], b1 = B[k=tig+4][n=gid]
    // B[k=c][n=m] = W[m][c][r][s], OIHW: flt[((m*8+c)*3+r)*3+s]
    uint32_t b0[9], b1[9];
    #pragma unroll
    for (int rs = 0; rs < 9; rs++) {
        int r = rs / 3, s = rs % 3;
        b0[rs] = f2tf32(flt[((gid * 8 + tig) * 3 + r) * 3 + s]);
        b1[rs] = f2tf32(flt[((gid * 8 + tig + 4) * 3 + r) * 3 + s]);
    }
    __syncthreads();

    // ---- 128 warp-jobs per block: 8 y-rows x 16 x-tiles of 16 px ----
    #pragma unroll 1
    for (int jj = 0; jj < 16; jj++) {
        const int J  = jj * 8 + w;
        const int yi = J >> 4;
        const int xt = J & 15;
        const int y  = y0 + yi;
        if (y >= P_OUT) continue;     // warp-uniform
        const int xb = xt * 16;

        float c0 = 0.f, c1 = 0.f, c2 = 0.f, c3 = 0.f;
        const float* base = sin_ + yi * ROW_STRIDE + xb + gid;

        #pragma unroll
        for (int r = 0; r < 3; r++) {
            const float* pr = base + r * ROW_STRIDE;
            #pragma unroll
            for (int s = 0; s < 3; s++) {
                // A layout: a0=A[gid][tig] a1=A[gid+8][tig] a2=A[gid][tig+4] a3=A[gid+8][tig+4]
                // A[px][k=c] = in[c][y+r][xb+px+s]
                uint32_t a0 = f2tf32(pr[tig * CH_STRIDE + s]);
                uint32_t a1 = f2tf32(pr[tig * CH_STRIDE + s + 8]);
                uint32_t a2 = f2tf32(pr[(tig + 4) * CH_STRIDE + s]);
                uint32_t a3 = f2tf32(pr[(tig + 4) * CH_STRIDE + s + 8]);
                const int rs = r * 3 + s;
                asm volatile(
                    "mma.sync.aligned.m16n8k8.row.col.f32.tf32.tf32.f32 "
                    "{%0,%1,%2,%3}, {%4,%5,%6,%7}, {%8,%9}, {%0,%1,%2,%3};"
                    : "+f"(c0), "+f"(c1), "+f"(c2), "+f"(c3)
                    : "r"(a0), "r"(a1), "r"(a2), "r"(a3),
                      "r"(b0[rs]), "r"(b1[rs]));
            }
        }

        // ---- store: C[row=px][col=m]; c0:(gid,2t) c1:(gid,2t+1) c2:(gid+8,2t) c3:(gid+8,2t+1)
        const int px = xb + gid;                 // <= 247, always valid
        float* ob = out + (size_t)(n * M_OUT) * PLANE + (size_t)y * P_OUT;
        ob[(2 * tig    ) * PLANE + px] = c0;
        ob[(2 * tig + 1) * PLANE + px] = c1;
        if (px + 8 < P_OUT) {
            ob[(2 * tig    ) * PLANE + px + 8] = c2;
            ob[(2 * tig + 1) * PLANE + px + 8] = c3;
        }
    }
}

extern "C" void kernel_launch(void* const* d_in, const int* in_sizes, int n_in,
                              void* d_out, int out_size) {
    const float* in  = (const float*)d_in[0];   // (64, 8, 256, 256) fp32
    const float* flt = (const float*)d_in[1];   // (8, 8, 3, 3) fp32 OIHW
    float* out = (float*)d_out;                 // (64, 8, 254, 254) fp32

    (void)in_sizes; (void)n_in; (void)out_size;

    cudaFuncSetAttribute(conv_mma_kernel,
                         cudaFuncAttributeMaxDynamicSharedMemorySize, SMEM_BYTES);

    dim3 grid((P_OUT + YB - 1) / YB, 64);   // 32 y-blocks x 64 n
    conv_mma_kernel<<<grid, 256, SMEM_BYTES>>>(in, flt, out);
}

// round 7
// speedup vs baseline: 3.7521x; 1.3285x over previous
#include <cuda_runtime.h>
#include <stdint.h>

// ---------------- problem constants ----------------
#define C_IN   8
#define HW     256
#define M_OUT  8
#define P_OUT  254
#define PLANE  (P_OUT * P_OUT)

// ---------------- tiling ----------------
#define YB        8                         // output rows per block
#define ROWS_ST   (YB + 2)                  // staged input rows
#define CH_STRIDE 264                       // uint32; 264 mod 32 == 8 -> conflict-free
#define ROW_STRIDE (C_IN * CH_STRIDE)       // 2112 per staged input row
#define SMEM_WORDS (ROWS_ST * ROW_STRIDE)   // 21120
#define SMEM_BYTES (SMEM_WORDS * 4)         // 84480

__device__ __forceinline__ uint32_t f2tf32(float f) {
    uint32_t r;
    asm("cvt.rna.tf32.f32 %0, %1;" : "=r"(r) : "f"(f));
    return r;
}

__device__ __forceinline__ void load_row(uint32_t* A, const uint32_t* p, int tig) {
    // 12 values: [ch2*6 + half*3 + s] ; ch = tig + ch2*4 ; pos = g + half*8 + s
    #pragma unroll
    for (int ch2 = 0; ch2 < 2; ch2++) {
        const uint32_t* q = p + (tig + ch2 * 4) * CH_STRIDE;
        A[ch2 * 6 + 0] = q[0];
        A[ch2 * 6 + 1] = q[1];
        A[ch2 * 6 + 2] = q[2];
        A[ch2 * 6 + 3] = q[8];
        A[ch2 * 6 + 4] = q[9];
        A[ch2 * 6 + 5] = q[10];
    }
}

__global__ __launch_bounds__(256, 2)
void conv_mma_kernel(const float* __restrict__ in,
                     const float* __restrict__ flt,
                     float* __restrict__ out) {
    extern __shared__ uint32_t sin_[];   // tf32 bits: [row 0..9][c 0..7][px, stride 264]

    const int tid  = threadIdx.x;
    const int w    = tid >> 5;
    const int lane = tid & 31;
    const int gid  = lane >> 2;       // 0..7  (pixel within fragment row group)
    const int tig  = lane & 3;        // 0..3  (channel group)
    const int n    = blockIdx.y;
    const int y0   = blockIdx.x * YB;

    // ---- stage input rows y0 .. y0+9 as TF32 bits (zero-fill OOB) ----
    const float* inb = in + (size_t)n * (C_IN * HW * HW);
    #pragma unroll
    for (int it = 0; it < 20; it++) {
        int i   = tid + it * 256;     // 0..5119
        int row = i >> 9;             // 10 rows
        int c   = (i >> 6) & 7;
        int x4  = i & 63;             // float4 within row
        int gy  = y0 + row;
        float4 v = make_float4(0.f, 0.f, 0.f, 0.f);
        if (gy < HW) v = *(const float4*)(inb + (c * HW + gy) * HW + x4 * 4);
        uint4 t = make_uint4(f2tf32(v.x), f2tf32(v.y), f2tf32(v.z), f2tf32(v.w));
        *(uint4*)(sin_ + row * ROW_STRIDE + c * CH_STRIDE + x4 * 4) = t;
    }
    // zero the pad columns 256..263 (ring loads may touch px 256..257)
    for (int i = tid; i < ROWS_ST * C_IN * 8; i += 256) {
        int row = i >> 6;
        int c   = (i >> 3) & 7;
        sin_[row * ROW_STRIDE + c * CH_STRIDE + 256 + (i & 7)] = 0u;
    }

    // ---- B fragments (weights) ----
    // b0 = W[m=gid][c=tig][r][s], b1 = W[gid][tig+4][r][s]  (OIHW)
    uint32_t b0[9], b1[9];
    #pragma unroll
    for (int rs = 0; rs < 9; rs++) {
        int r = rs / 3, s = rs % 3;
        b0[rs] = f2tf32(flt[((gid * 8 + tig) * 3 + r) * 3 + s]);
        b1[rs] = f2tf32(flt[((gid * 8 + tig + 4) * 3 + r) * 3 + s]);
    }
    __syncthreads();

    // ---- each warp: 2 x-columns of 16 px, sweeping 8 y-rows with a 3-row ring ----
    #pragma unroll 1
    for (int col = 0; col < 2; col++) {
        const int xt = w + col * 8;         // 0..15
        const int xb = xt * 16;
        const int g  = xb + gid;            // output px (first group), <= 247
        const uint32_t* base = sin_ + g;

        uint32_t A[3][12];
        load_row(A[0], base + 0 * ROW_STRIDE, tig);
        load_row(A[1], base + 1 * ROW_STRIDE, tig);

        #pragma unroll
        for (int yi = 0; yi < YB; yi++) {
            load_row(A[(yi + 2) % 3], base + (yi + 2) * ROW_STRIDE, tig);

            float c0 = 0.f, c1 = 0.f, c2 = 0.f, c3 = 0.f;
            #pragma unroll
            for (int r = 0; r < 3; r++) {
                const uint32_t* Ar = A[(yi + r) % 3];
                #pragma unroll
                for (int s = 0; s < 3; s++) {
                    const int rs = r * 3 + s;
                    asm volatile(
                        "mma.sync.aligned.m16n8k8.row.col.f32.tf32.tf32.f32 "
                        "{%0,%1,%2,%3}, {%4,%5,%6,%7}, {%8,%9}, {%0,%1,%2,%3};"
                        : "+f"(c0), "+f"(c1), "+f"(c2), "+f"(c3)
                        : "r"(Ar[s]), "r"(Ar[3 + s]), "r"(Ar[6 + s]), "r"(Ar[9 + s]),
                          "r"(b0[rs]), "r"(b1[rs]));
                }
            }

            const int y = y0 + yi;
            if (y < P_OUT) {
                // C layout: c0:(px=g, m=2*tig) c1:(g, 2*tig+1) c2:(g+8, 2*tig) c3:(g+8, 2*tig+1)
                float* ob = out + (size_t)(n * M_OUT) * PLANE + (size_t)y * P_OUT;
                ob[(2 * tig    ) * PLANE + g] = c0;
                ob[(2 * tig + 1) * PLANE + g] = c1;
                if (g + 8 < P_OUT) {
                    ob[(2 * tig    ) * PLANE + g + 8] = c2;
                    ob[(2 * tig + 1) * PLANE + g + 8] = c3;
                }
            }
        }
    }
}

extern "C" void kernel_launch(void* const* d_in, const int* in_sizes, int n_in,
                              void* d_out, int out_size) {
    const float* in  = (const float*)d_in[0];   // (64, 8, 256, 256) fp32
    const float* flt = (const float*)d_in[1];   // (8, 8, 3, 3) fp32 OIHW
    float* out = (float*)d_out;                 // (64, 8, 254, 254) fp32

    (void)in_sizes; (void)n_in; (void)out_size;

    cudaFuncSetAttribute(conv_mma_kernel,
                         cudaFuncAttributeMaxDynamicSharedMemorySize, SMEM_BYTES);

    dim3 grid((P_OUT + YB - 1) / YB, 64);   // 32 y-blocks x 64 n
    conv_mma_kernel<<<grid, 256, SMEM_BYTES>>>(in, flt, out);
}